// round 4
// baseline (speedup 1.0000x reference)
#include <cuda_runtime.h>

#define N_      16384
#define K_      64
#define F_      2048
#define NCHUNK  4
#define CHUNK   512          // floats per F-chunk (256 threads x float2)
#define ALPHA_F 1.0f
#define GAMMA_F 1.0f

// ---- scratch (static device globals: allocation-free) ----
__device__ int   g_idx[N_];
__device__ int   g_rows[K_ * N_];     // per-cluster member row lists (stride N_)
__device__ int   g_cnt[K_];
__device__ float g_csum[F_];
__device__ float g_norm[K_];
__device__ float g_dot[K_];
__device__ float g_ak[K_];            // cw[k] / (row_sum[k]+alpha)
__device__ float g_invden[K_];        // 1 / (row_sum[k]+alpha)

// csum[f] = sum_k C[k,f]
__global__ void csum_k(const float* __restrict__ C) {
    int col = blockIdx.x * blockDim.x + threadIdx.x;
    float s = 0.f;
#pragma unroll
    for (int k = 0; k < K_; k++) s += C[k * F_ + col];
    g_csum[col] = s;
}

// per-k: norm[k] = ||c_k||^2,  dot[k] = c_k . csum
__global__ void normdot_k(const float* __restrict__ C) {
    int k = blockIdx.x, tid = threadIdx.x;
    float nn = 0.f, dd = 0.f;
    for (int f = tid; f < F_; f += 256) {
        float c = C[k * F_ + f];
        nn += c * c;
        dd += c * g_csum[f];
    }
#pragma unroll
    for (int o = 16; o; o >>= 1) {
        nn += __shfl_xor_sync(0xFFFFFFFFu, nn, o);
        dd += __shfl_xor_sync(0xFFFFFFFFu, dd, o);
    }
    __shared__ float sn[8], sd[8];
    int w = tid >> 5, l = tid & 31;
    if (l == 0) { sn[w] = nn; sd[w] = dd; }
    __syncthreads();
    if (tid == 0) {
        float a = 0.f, b = 0.f;
#pragma unroll
        for (int i = 0; i < 8; i++) { a += sn[i]; b += sd[i]; }
        g_norm[k] = a; g_dot[k] = b;
    }
}

// row_sum[k] = K*norm[k] + sum(norm) - 2*dot[k];  a_k, invden
__global__ void finalize_k(const float* __restrict__ cw) {
    __shared__ float tot;
    int t = threadIdx.x;           // 64 threads
    if (t == 0) {
        float s = 0.f;
        for (int i = 0; i < K_; i++) s += g_norm[i];
        tot = s;
    }
    __syncthreads();
    float rs  = (float)K_ * g_norm[t] + tot - 2.f * g_dot[t];
    float inv = 1.f / (rs + ALPHA_F);
    g_invden[t] = inv;
    g_ak[t]     = cw[t] * inv;
}

// warp-per-row argmax of one-hot labels (exact 1.0f -> ballot on >0.5)
// also zero-init the loss region of d_out (poisoned by harness)
__global__ void idx_k(const float* __restrict__ labels, float* __restrict__ loss) {
    int tid = threadIdx.x;
    int w = tid >> 5, l = tid & 31;
    int row = blockIdx.x * 8 + w;
    float v0 = labels[row * K_ + l];
    float v1 = labels[row * K_ + 32 + l];
    unsigned b0 = __ballot_sync(0xFFFFFFFFu, v0 > 0.5f);
    unsigned b1 = __ballot_sync(0xFFFFFFFFu, v1 > 0.5f);
    int id = b0 ? (__ffs(b0) - 1) : (31 + __ffs(b1));
    if (l == 0) { g_idx[row] = id; loss[row] = 0.f; }
}

// stable (deterministic) compaction: block k gathers its member rows in order
__global__ void bucket_k() {
    int k = blockIdx.x, tid = threadIdx.x;
    int w = tid >> 5, l = tid & 31;
    __shared__ int wcnt[8];
    unsigned lmask = (1u << l) - 1u;
    int base = 0;                       // every thread tracks base identically
    for (int t0 = 0; t0 < N_; t0 += 256) {
        int n = t0 + tid;
        int pred = (g_idx[n] == k);
        unsigned b = __ballot_sync(0xFFFFFFFFu, pred);
        if (l == 0) wcnt[w] = __popc(b);
        __syncthreads();
        int woff = 0, tot = 0;
#pragma unroll
        for (int j = 0; j < 8; j++) { int c = wcnt[j]; tot += c; if (j < w) woff += c; }
        if (pred) g_rows[k * N_ + base + woff + __popc(b & lmask)] = n;
        base += tot;
        __syncthreads();                // protect wcnt reuse next iter
    }
    if (tid == 0) g_cnt[k] = base;
}

// main fused pass: block (chunk c, cluster k); thread owns float2 column pair.
// - accumulates Sx[k, cols] in registers
// - per-row ||x-c||^2 partial -> warp reduce -> atomicAdd(loss[n], s*invden_k)
// - epilogue writes new_cluster[k, cols] directly (exclusive ownership)
__global__ void __launch_bounds__(256) main_k(const float* __restrict__ X,
                                              const float* __restrict__ C,
                                              float* __restrict__ out) {
    int c   = blockIdx.x;
    int k   = blockIdx.y;
    int tid = threadIdx.x;
    int l   = tid & 31;
    int col = c * CHUNK + 2 * tid;

    float2 ck = *(const float2*)(C + k * F_ + col);
    float ax = 0.f, ay = 0.f;
    int   cnt  = g_cnt[k];
    float invd = g_invden[k];
    float* loss = out;                              // loss lives at out[0..N)

    __shared__ int srows[64];
    const int* rl = g_rows + k * N_;

    for (int rb = 0; rb < cnt; rb += 64) {
        int m = min(64, cnt - rb);
        if (tid < m) srows[tid] = rl[rb + tid];
        __syncthreads();
#pragma unroll 4
        for (int i = 0; i < m; i++) {
            int n = srows[i];
            float2 x = *(const float2*)(X + (size_t)n * F_ + col);
            float dx = x.x - ck.x, dy = x.y - ck.y;
            float s = dx * dx + dy * dy;
            ax += x.x; ay += x.y;
#pragma unroll
            for (int o = 16; o; o >>= 1) s += __shfl_xor_sync(0xFFFFFFFFu, s, o);
            if (l == 0) atomicAdd(loss + n, s * invd);
        }
        __syncthreads();
    }

    float ak = g_ak[k];
    float fc = (float)cnt;
    float2 o;
    o.x = ck.x - GAMMA_F * ak * (ax - fc * ck.x);
    o.y = ck.y - GAMMA_F * ak * (ay - fc * ck.y);
    *(float2*)(out + N_ + k * F_ + col) = o;
}

extern "C" void kernel_launch(void* const* d_in, const int* in_sizes, int n_in,
                              void* d_out, int out_size) {
    const float* X  = (const float*)d_in[0];   // features [N,F]
    const float* L  = (const float*)d_in[1];   // labels   [N,K] one-hot
    const float* C  = (const float*)d_in[2];   // cluster  [K,F]
    const float* CW = (const float*)d_in[3];   // class_weight [K]
    float* out = (float*)d_out;                // [loss(N) | new_cluster(K*F)]

    csum_k    <<<F_ / 256, 256>>>(C);
    normdot_k <<<K_, 256>>>(C);
    finalize_k<<<1, K_>>>(CW);
    idx_k     <<<N_ / 8, 256>>>(L, out);
    bucket_k  <<<K_, 256>>>();
    main_k    <<<dim3(NCHUNK, K_), 256>>>(X, C, out);
}

// round 5
// speedup vs baseline: 1.9777x; 1.9777x over previous
#include <cuda_runtime.h>

#define N_      16384
#define K_      64
#define F_      2048
#define NCHUNK  4
#define CHUNK   512          // floats per F-chunk (128 threads x float4)
#define TPB     128
#define ALPHA_F 1.0f
#define GAMMA_F 1.0f

// ---- scratch (static device globals: allocation-free) ----
__device__ int   g_idx[N_];
__device__ int   g_rows[K_ * N_];     // per-cluster member row lists (stride N_)
__device__ int   g_cnt[K_];
__device__ float g_csum[F_];
__device__ float g_norm[K_];
__device__ float g_dot[K_];
__device__ float g_ak[K_];            // cw[k] / (row_sum[k]+alpha)
__device__ float g_invden[K_];        // 1 / (row_sum[k]+alpha)

// csum[f] = sum_k C[k,f]
__global__ void csum_k(const float* __restrict__ C) {
    int col = blockIdx.x * blockDim.x + threadIdx.x;
    float s = 0.f;
#pragma unroll
    for (int k = 0; k < K_; k++) s += C[k * F_ + col];
    g_csum[col] = s;
}

// per-k: norm[k] = ||c_k||^2,  dot[k] = c_k . csum
__global__ void normdot_k(const float* __restrict__ C) {
    int k = blockIdx.x, tid = threadIdx.x;
    float nn = 0.f, dd = 0.f;
    for (int f = tid; f < F_; f += 256) {
        float c = C[k * F_ + f];
        nn += c * c;
        dd += c * g_csum[f];
    }
#pragma unroll
    for (int o = 16; o; o >>= 1) {
        nn += __shfl_xor_sync(0xFFFFFFFFu, nn, o);
        dd += __shfl_xor_sync(0xFFFFFFFFu, dd, o);
    }
    __shared__ float sn[8], sd[8];
    int w = tid >> 5, l = tid & 31;
    if (l == 0) { sn[w] = nn; sd[w] = dd; }
    __syncthreads();
    if (tid == 0) {
        float a = 0.f, b = 0.f;
#pragma unroll
        for (int i = 0; i < 8; i++) { a += sn[i]; b += sd[i]; }
        g_norm[k] = a; g_dot[k] = b;
    }
}

// row_sum[k] = K*norm[k] + sum(norm) - 2*dot[k];  a_k, invden
__global__ void finalize_k(const float* __restrict__ cw) {
    __shared__ float tot;
    int t = threadIdx.x;           // 64 threads
    if (t == 0) {
        float s = 0.f;
        for (int i = 0; i < K_; i++) s += g_norm[i];
        tot = s;
    }
    __syncthreads();
    float rs  = (float)K_ * g_norm[t] + tot - 2.f * g_dot[t];
    float inv = 1.f / (rs + ALPHA_F);
    g_invden[t] = inv;
    g_ak[t]     = cw[t] * inv;
}

// half-warp-per-row argmax of one-hot labels (exact 1.0f -> threshold 0.5)
// each lane16 loads float4 (4 labels); min-reduce of first-hot position.
// also zero-init the loss region of d_out (poisoned by harness)
__global__ void idx_k(const float* __restrict__ labels, float* __restrict__ loss) {
    int tid = threadIdx.x;
    int w = tid >> 5, l = tid & 31;
    int half = l >> 4, lane16 = l & 15;
    int row = blockIdx.x * 16 + w * 2 + half;
    float4 v = reinterpret_cast<const float4*>(labels + row * K_)[lane16];
    int loc = (v.x > 0.5f) ? 0 : (v.y > 0.5f) ? 1 : (v.z > 0.5f) ? 2 : 3;
    bool pred = (v.x > 0.5f) | (v.y > 0.5f) | (v.z > 0.5f) | (v.w > 0.5f);
    int val = pred ? (lane16 * 4 + loc) : (1 << 30);
#pragma unroll
    for (int o = 8; o; o >>= 1)
        val = min(val, __shfl_xor_sync(0xFFFFFFFFu, val, o));
    if (lane16 == 0) { g_idx[row] = val; loss[row] = 0.f; }
}

// stable (deterministic) compaction: block k gathers its member rows.
// int4 scan: 1024 ids per outer iteration, 4 ballots per barrier pair.
__global__ void bucket_k() {
    int k = blockIdx.x, tid = threadIdx.x;
    int w = tid >> 5, l = tid & 31;
    __shared__ int wcnt[8][4];
    unsigned lmask = (1u << l) - 1u;
    int base = 0;                       // every thread tracks base identically
    for (int t0 = 0; t0 < N_; t0 += 1024) {
        int4 v = *reinterpret_cast<const int4*>(g_idx + t0 + 4 * tid);
        int pred[4] = { v.x == k, v.y == k, v.z == k, v.w == k };
        unsigned b[4];
#pragma unroll
        for (int e = 0; e < 4; e++) {
            b[e] = __ballot_sync(0xFFFFFFFFu, pred[e]);
            if (l == 0) wcnt[w][e] = __popc(b[e]);
        }
        __syncthreads();
        int run = 0;
#pragma unroll
        for (int e = 0; e < 4; e++) {
            int woff = 0, tote = 0;
#pragma unroll
            for (int j = 0; j < 8; j++) {
                int c = wcnt[j][e];
                tote += c;
                if (j < w) woff += c;
            }
            if (pred[e])
                g_rows[k * N_ + base + run + woff + __popc(b[e] & lmask)]
                    = t0 + 4 * tid + e;
            run += tote;
        }
        base += run;
        __syncthreads();                // protect wcnt reuse next iter
    }
    if (tid == 0) g_cnt[k] = base;
}

// main fused pass: block (chunk c, cluster k); thread owns float4 (4 cols).
// Explicit 8-row register prefetch => MLP=8 per warp (latency fix).
// - accumulates Sx[k, cols] in registers
// - per-row partial ||x-c||^2 -> 5-shuffle reduce -> atomicAdd(loss[n])
// - epilogue writes new_cluster[k, cols] directly (exclusive ownership)
__global__ void __launch_bounds__(TPB) main_k(const float* __restrict__ X,
                                              const float* __restrict__ C,
                                              float* __restrict__ out) {
    int c   = blockIdx.x;
    int k   = blockIdx.y;
    int tid = threadIdx.x;
    int l   = tid & 31;
    int col = c * CHUNK + 4 * tid;

    float4 ck = *reinterpret_cast<const float4*>(C + k * F_ + col);
    float ax = 0.f, ay = 0.f, az = 0.f, aw = 0.f;
    int   cnt  = g_cnt[k];
    float invd = g_invden[k];
    float* loss = out;                              // loss lives at out[0..N)

    __shared__ int srows[TPB];
    const int* rl = g_rows + k * N_;

    for (int rb = 0; rb < cnt; rb += TPB) {
        int m = min(TPB, cnt - rb);
        if (tid < m) srows[tid] = rl[rb + tid];
        __syncthreads();
        int i = 0;
        for (; i + 8 <= m; i += 8) {
            int   n[8];
            float4 x[8];
#pragma unroll
            for (int j = 0; j < 8; j++) n[j] = srows[i + j];
#pragma unroll
            for (int j = 0; j < 8; j++)
                x[j] = *reinterpret_cast<const float4*>(X + (size_t)n[j] * F_ + col);
#pragma unroll
            for (int j = 0; j < 8; j++) {
                float dx = x[j].x - ck.x, dy = x[j].y - ck.y;
                float dz = x[j].z - ck.z, dw = x[j].w - ck.w;
                float s = dx * dx + dy * dy + dz * dz + dw * dw;
                ax += x[j].x; ay += x[j].y; az += x[j].z; aw += x[j].w;
#pragma unroll
                for (int o = 16; o; o >>= 1)
                    s += __shfl_xor_sync(0xFFFFFFFFu, s, o);
                if (l == 0) atomicAdd(loss + n[j], s * invd);
            }
        }
        for (; i < m; i++) {                         // tail
            int n = srows[i];
            float4 x = *reinterpret_cast<const float4*>(X + (size_t)n * F_ + col);
            float dx = x.x - ck.x, dy = x.y - ck.y;
            float dz = x.z - ck.z, dw = x.w - ck.w;
            float s = dx * dx + dy * dy + dz * dz + dw * dw;
            ax += x.x; ay += x.y; az += x.z; aw += x.w;
#pragma unroll
            for (int o = 16; o; o >>= 1)
                s += __shfl_xor_sync(0xFFFFFFFFu, s, o);
            if (l == 0) atomicAdd(loss + n, s * invd);
        }
        __syncthreads();
    }

    float ak = g_ak[k];
    float fc = (float)cnt;
    float4 o;
    o.x = ck.x - GAMMA_F * ak * (ax - fc * ck.x);
    o.y = ck.y - GAMMA_F * ak * (ay - fc * ck.y);
    o.z = ck.z - GAMMA_F * ak * (az - fc * ck.z);
    o.w = ck.w - GAMMA_F * ak * (aw - fc * ck.w);
    *reinterpret_cast<float4*>(out + N_ + k * F_ + col) = o;
}

extern "C" void kernel_launch(void* const* d_in, const int* in_sizes, int n_in,
                              void* d_out, int out_size) {
    const float* X  = (const float*)d_in[0];   // features [N,F]
    const float* L  = (const float*)d_in[1];   // labels   [N,K] one-hot
    const float* C  = (const float*)d_in[2];   // cluster  [K,F]
    const float* CW = (const float*)d_in[3];   // class_weight [K]
    float* out = (float*)d_out;                // [loss(N) | new_cluster(K*F)]

    csum_k    <<<F_ / 256, 256>>>(C);
    normdot_k <<<K_, 256>>>(C);
    finalize_k<<<1, K_>>>(CW);
    idx_k     <<<N_ / 16, 256>>>(L, out);
    bucket_k  <<<K_, 256>>>();
    main_k    <<<dim3(NCHUNK, K_), 256 / 2>>>(X, C, out);
}

// round 6
// speedup vs baseline: 3.3490x; 1.6933x over previous
#include <cuda_runtime.h>

#define N_      16384
#define K_      64
#define F_      2048
#define NCHUNK  4
#define CHUNK   512          // floats per F-chunk (128 threads x float4)
#define TPB     128
#define S_      8            // row segments per cluster
#define ALPHA_F 1.0f
#define GAMMA_F 1.0f

// ---- scratch (static device globals: allocation-free) ----
__device__ int   g_idx[N_];
__device__ int   g_rows[K_ * N_];        // per-cluster member row lists (stride N_)
__device__ int   g_cnt[K_];
__device__ float g_csum[F_];
__device__ float g_norm[K_];
__device__ float g_dot[K_];
__device__ float g_ak[K_];               // cw[k] / (row_sum[k]+alpha)
__device__ float g_invden[K_];           // 1 / (row_sum[k]+alpha)
__device__ float g_sx[S_ * K_ * F_];     // per-segment column-sum partials (4 MB)

// csum[f] = sum_k C[k,f]
__global__ void csum_k(const float* __restrict__ C) {
    int col = blockIdx.x * blockDim.x + threadIdx.x;
    float s = 0.f;
#pragma unroll
    for (int k = 0; k < K_; k++) s += C[k * F_ + col];
    g_csum[col] = s;
}

// per-k: norm[k] = ||c_k||^2,  dot[k] = c_k . csum
__global__ void normdot_k(const float* __restrict__ C) {
    int k = blockIdx.x, tid = threadIdx.x;
    float nn = 0.f, dd = 0.f;
    for (int f = tid; f < F_; f += 256) {
        float c = C[k * F_ + f];
        nn += c * c;
        dd += c * g_csum[f];
    }
#pragma unroll
    for (int o = 16; o; o >>= 1) {
        nn += __shfl_xor_sync(0xFFFFFFFFu, nn, o);
        dd += __shfl_xor_sync(0xFFFFFFFFu, dd, o);
    }
    __shared__ float sn[8], sd[8];
    int w = tid >> 5, l = tid & 31;
    if (l == 0) { sn[w] = nn; sd[w] = dd; }
    __syncthreads();
    if (tid == 0) {
        float a = 0.f, b = 0.f;
#pragma unroll
        for (int i = 0; i < 8; i++) { a += sn[i]; b += sd[i]; }
        g_norm[k] = a; g_dot[k] = b;
    }
}

// row_sum[k] = K*norm[k] + sum(norm) - 2*dot[k];  a_k, invden
__global__ void finalize_k(const float* __restrict__ cw) {
    __shared__ float tot;
    int t = threadIdx.x;           // 64 threads
    if (t == 0) {
        float s = 0.f;
        for (int i = 0; i < K_; i++) s += g_norm[i];
        tot = s;
    }
    __syncthreads();
    float rs  = (float)K_ * g_norm[t] + tot - 2.f * g_dot[t];
    float inv = 1.f / (rs + ALPHA_F);
    g_invden[t] = inv;
    g_ak[t]     = cw[t] * inv;
}

// one row per thread; labels exact one-hot => idx = sum_i v[i]*i (exact fp32).
// 16 independent float4 loads per thread (MLP=16). Also zero-init loss region.
__global__ void idx_k(const float* __restrict__ labels, float* __restrict__ loss) {
    int row = blockIdx.x * TPB + threadIdx.x;
    const float4* p = reinterpret_cast<const float4*>(labels + row * K_);
    float4 v[16];
#pragma unroll
    for (int j = 0; j < 16; j++) v[j] = p[j];
    float acc = 0.f;
#pragma unroll
    for (int j = 0; j < 16; j++) {
        acc += v[j].x * (float)(4 * j)
             + v[j].y * (float)(4 * j + 1)
             + v[j].z * (float)(4 * j + 2)
             + v[j].w * (float)(4 * j + 3);
    }
    g_idx[row] = (int)(acc + 0.5f);
    loss[row] = 0.f;
}

// stable (deterministic) compaction: block k gathers its member rows.
__global__ void bucket_k() {
    int k = blockIdx.x, tid = threadIdx.x;
    int w = tid >> 5, l = tid & 31;
    __shared__ int wcnt[8][4];
    unsigned lmask = (1u << l) - 1u;
    int base = 0;
    for (int t0 = 0; t0 < N_; t0 += 1024) {
        int4 v = *reinterpret_cast<const int4*>(g_idx + t0 + 4 * tid);
        int pred[4] = { v.x == k, v.y == k, v.z == k, v.w == k };
        unsigned b[4];
#pragma unroll
        for (int e = 0; e < 4; e++) {
            b[e] = __ballot_sync(0xFFFFFFFFu, pred[e]);
            if (l == 0) wcnt[w][e] = __popc(b[e]);
        }
        __syncthreads();
        int run = 0;
#pragma unroll
        for (int e = 0; e < 4; e++) {
            int woff = 0, tote = 0;
#pragma unroll
            for (int j = 0; j < 8; j++) {
                int c = wcnt[j][e];
                tote += c;
                if (j < w) woff += c;
            }
            if (pred[e])
                g_rows[k * N_ + base + run + woff + __popc(b[e] & lmask)]
                    = t0 + 4 * tid + e;
            run += tote;
        }
        base += run;
        __syncthreads();
    }
    if (tid == 0) g_cnt[k] = base;
}

// main fused pass: block (chunk c, cluster k, segment s).
// Segment partial column-sums -> g_sx (exclusive ownership, no atomics).
// Loss: 8-row batch, pair-combine multi-value warp reduce (16 shuffles),
// then ONE 8-lane REDG per batch.
__global__ void __launch_bounds__(TPB) main_k(const float* __restrict__ X,
                                              const float* __restrict__ C,
                                              float* __restrict__ out) {
    int c   = blockIdx.x;
    int k   = blockIdx.y;
    int seg = blockIdx.z;
    int tid = threadIdx.x;
    int l   = tid & 31;
    int col = c * CHUNK + 4 * tid;

    float4 ck = *reinterpret_cast<const float4*>(C + k * F_ + col);
    float ax = 0.f, ay = 0.f, az = 0.f, aw = 0.f;
    int   cnt  = g_cnt[k];
    float invd = g_invden[k];
    float* loss = out;                          // loss at out[0..N)

    int r0 = (cnt * seg) / S_;
    int r1 = (cnt * (seg + 1)) / S_;

    __shared__ int srows[TPB];
    const int* rl = g_rows + k * N_;

    for (int rb = r0; rb < r1; rb += TPB) {
        int m = min(TPB, r1 - rb);
        if (tid < m) srows[tid] = rl[rb + tid];
        __syncthreads();
        int i = 0;
        for (; i + 8 <= m; i += 8) {
            float4 x[8];
#pragma unroll
            for (int j = 0; j < 8; j++)
                x[j] = *reinterpret_cast<const float4*>(
                    X + (size_t)srows[i + j] * F_ + col);
            float s[8];
#pragma unroll
            for (int j = 0; j < 8; j++) {
                float dx = x[j].x - ck.x, dy = x[j].y - ck.y;
                float dz = x[j].z - ck.z, dw = x[j].w - ck.w;
                s[j] = dx * dx + dy * dy + dz * dz + dw * dw;
                ax += x[j].x; ay += x[j].y; az += x[j].z; aw += x[j].w;
            }
            // multi-value reduce: 8 values across 32 lanes in 16 shuffles.
            float cc[4];
#pragma unroll
            for (int p = 0; p < 4; p++) {
                float t0 = __shfl_xor_sync(0xFFFFFFFFu, s[2 * p], 16);
                float t1 = __shfl_xor_sync(0xFFFFFFFFu, s[2 * p + 1], 16);
                cc[p] = (l & 16) ? (s[2 * p + 1] + t1) : (s[2 * p] + t0);
            }
            float dd_[2];
#pragma unroll
            for (int p = 0; p < 2; p++) {
                float t0 = __shfl_xor_sync(0xFFFFFFFFu, cc[2 * p], 8);
                float t1 = __shfl_xor_sync(0xFFFFFFFFu, cc[2 * p + 1], 8);
                dd_[p] = (l & 8) ? (cc[2 * p + 1] + t1) : (cc[2 * p] + t0);
            }
            float t0 = __shfl_xor_sync(0xFFFFFFFFu, dd_[0], 4);
            float t1 = __shfl_xor_sync(0xFFFFFFFFu, dd_[1], 4);
            float e  = (l & 4) ? (dd_[1] + t1) : (dd_[0] + t0);
            e += __shfl_xor_sync(0xFFFFFFFFu, e, 2);
            e += __shfl_xor_sync(0xFFFFFFFFu, e, 1);
            // lane 4m holds total for row j = bit-reverse3(m)
            if ((l & 3) == 0) {
                int mm = l >> 2;
                int j = ((mm & 1) << 2) | (mm & 2) | (mm >> 2);
                atomicAdd(loss + srows[i + j], e * invd);
            }
        }
        for (; i < m; i++) {                    // tail rows
            float4 x = *reinterpret_cast<const float4*>(
                X + (size_t)srows[i] * F_ + col);
            float dx = x.x - ck.x, dy = x.y - ck.y;
            float dz = x.z - ck.z, dw = x.w - ck.w;
            float s = dx * dx + dy * dy + dz * dz + dw * dw;
            ax += x.x; ay += x.y; az += x.z; aw += x.w;
#pragma unroll
            for (int o = 16; o; o >>= 1)
                s += __shfl_xor_sync(0xFFFFFFFFu, s, o);
            if (l == 0) atomicAdd(loss + srows[i], s * invd);
        }
        __syncthreads();
    }

    float4 p4 = make_float4(ax, ay, az, aw);
    *reinterpret_cast<float4*>(g_sx + ((size_t)seg * K_ + k) * F_ + col) = p4;
}

// fold segment partials + epilogue: new_cluster = ck - g*ak*(Sx - cnt*ck)
__global__ void reduce_k(const float* __restrict__ C, float* __restrict__ out) {
    int t  = blockIdx.x * TPB + threadIdx.x;    // over K_*F_/4
    int k  = t / (F_ / 4);
    int cv = t % (F_ / 4);
    float4 sum = make_float4(0.f, 0.f, 0.f, 0.f);
#pragma unroll
    for (int s = 0; s < S_; s++) {
        float4 v = *reinterpret_cast<const float4*>(
            g_sx + ((size_t)s * K_ + k) * F_ + 4 * cv);
        sum.x += v.x; sum.y += v.y; sum.z += v.z; sum.w += v.w;
    }
    float4 ck = reinterpret_cast<const float4*>(C + k * F_)[cv];
    float ga = GAMMA_F * g_ak[k];
    float fc = (float)g_cnt[k];
    float4 o;
    o.x = ck.x - ga * (sum.x - fc * ck.x);
    o.y = ck.y - ga * (sum.y - fc * ck.y);
    o.z = ck.z - ga * (sum.z - fc * ck.z);
    o.w = ck.w - ga * (sum.w - fc * ck.w);
    reinterpret_cast<float4*>(out + N_ + k * F_)[cv] = o;
}

extern "C" void kernel_launch(void* const* d_in, const int* in_sizes, int n_in,
                              void* d_out, int out_size) {
    const float* X  = (const float*)d_in[0];   // features [N,F]
    const float* L  = (const float*)d_in[1];   // labels   [N,K] one-hot
    const float* C  = (const float*)d_in[2];   // cluster  [K,F]
    const float* CW = (const float*)d_in[3];   // class_weight [K]
    float* out = (float*)d_out;                // [loss(N) | new_cluster(K*F)]

    csum_k    <<<F_ / 256, 256>>>(C);
    normdot_k <<<K_, 256>>>(C);
    finalize_k<<<1, K_>>>(CW);
    idx_k     <<<N_ / TPB, TPB>>>(L, out);
    bucket_k  <<<K_, 256>>>();
    main_k    <<<dim3(NCHUNK, K_, S_), TPB>>>(X, C, out);
    reduce_k  <<<(K_ * F_ / 4) / TPB, TPB>>>(C, out);
}

// round 7
// speedup vs baseline: 3.5899x; 1.0719x over previous
#include <cuda_runtime.h>

#define N_      16384
#define K_      64
#define F_      2048
#define NCHUNK  4
#define CHUNK   512          // floats per F-chunk (128 threads x float4)
#define TPB     128
#define S_      8            // row segments per cluster
#define ALPHA_F 1.0f
#define GAMMA_F 1.0f

// ---- scratch (static device globals: allocation-free) ----
__device__ int   g_idx[N_];
__device__ int   g_rows[K_ * N_];        // per-cluster member row lists (stride N_)
__device__ int   g_cnt[K_];
__device__ float g_ak[K_];               // cw[k] / (row_sum[k]+alpha)
__device__ float g_invden[K_];           // 1 / (row_sum[k]+alpha)
__device__ float g_sx[S_ * K_ * F_];     // per-segment column-sum partials (4 MB)

// ---------------------------------------------------------------------------
// prep_k: block k computes rs_k = sum_j ||c_k - c_j||^2 directly (C stays in
// L2: 64 blocks x 512KB = 32MB L2 traffic), then ak/invden. Replaces the old
// csum/normdot/finalize 3-kernel chain.
// ---------------------------------------------------------------------------
__global__ void __launch_bounds__(256) prep_k(const float* __restrict__ C,
                                              const float* __restrict__ cw) {
    int k = blockIdx.x, tid = threadIdx.x;
    // each thread owns 8 columns: [8*tid, 8*tid+8)
    float4 a0 = *reinterpret_cast<const float4*>(C + k * F_ + 8 * tid);
    float4 a1 = *reinterpret_cast<const float4*>(C + k * F_ + 8 * tid + 4);
    float acc = 0.f;
#pragma unroll 4
    for (int j = 0; j < K_; j++) {
        float4 b0 = *reinterpret_cast<const float4*>(C + j * F_ + 8 * tid);
        float4 b1 = *reinterpret_cast<const float4*>(C + j * F_ + 8 * tid + 4);
        float d0 = a0.x - b0.x, d1 = a0.y - b0.y, d2 = a0.z - b0.z, d3 = a0.w - b0.w;
        float d4 = a1.x - b1.x, d5 = a1.y - b1.y, d6 = a1.z - b1.z, d7 = a1.w - b1.w;
        acc += d0 * d0 + d1 * d1 + d2 * d2 + d3 * d3
             + d4 * d4 + d5 * d5 + d6 * d6 + d7 * d7;
    }
#pragma unroll
    for (int o = 16; o; o >>= 1) acc += __shfl_xor_sync(0xFFFFFFFFu, acc, o);
    __shared__ float sw_[8];
    int w = tid >> 5, l = tid & 31;
    if (l == 0) sw_[w] = acc;
    __syncthreads();
    if (tid == 0) {
        float rs = 0.f;
#pragma unroll
        for (int i = 0; i < 8; i++) rs += sw_[i];
        float inv = 1.f / (rs + ALPHA_F);
        g_invden[k] = inv;
        g_ak[k]     = cw[k] * inv;
    }
}

// ---------------------------------------------------------------------------
// idx_k: 4 threads per row. labels exact one-hot => idx = sum_i v[i]*i
// (exact in fp32). 4 independent float4 loads/thread + 2-shuffle reduce.
// Also zero-inits the loss region of d_out (poisoned by harness).
// ---------------------------------------------------------------------------
__global__ void idx_k(const float* __restrict__ labels, float* __restrict__ loss) {
    int t = blockIdx.x * TPB + threadIdx.x;
    int row = t >> 2, part = t & 3;
    const float4* p = reinterpret_cast<const float4*>(labels + row * K_) + part * 4;
    float acc = 0.f;
#pragma unroll
    for (int j = 0; j < 4; j++) {
        float4 v = p[j];
        float base = (float)(part * 16 + j * 4);
        acc += v.x * base + v.y * (base + 1.f) + v.z * (base + 2.f) + v.w * (base + 3.f);
    }
    acc += __shfl_xor_sync(0xFFFFFFFFu, acc, 1);
    acc += __shfl_xor_sync(0xFFFFFFFFu, acc, 2);
    if (part == 0) { g_idx[row] = (int)(acc + 0.5f); loss[row] = 0.f; }
}

// ---------------------------------------------------------------------------
// bucket_k: stable (deterministic) compaction, block k gathers member rows.
// ---------------------------------------------------------------------------
__global__ void bucket_k() {
    int k = blockIdx.x, tid = threadIdx.x;
    int w = tid >> 5, l = tid & 31;
    __shared__ int wcnt[8][4];
    unsigned lmask = (1u << l) - 1u;
    int base = 0;
    for (int t0 = 0; t0 < N_; t0 += 1024) {
        int4 v = *reinterpret_cast<const int4*>(g_idx + t0 + 4 * tid);
        int pred[4] = { v.x == k, v.y == k, v.z == k, v.w == k };
        unsigned b[4];
#pragma unroll
        for (int e = 0; e < 4; e++) {
            b[e] = __ballot_sync(0xFFFFFFFFu, pred[e]);
            if (l == 0) wcnt[w][e] = __popc(b[e]);
        }
        __syncthreads();
        int run = 0;
#pragma unroll
        for (int e = 0; e < 4; e++) {
            int woff = 0, tote = 0;
#pragma unroll
            for (int j = 0; j < 8; j++) {
                int c = wcnt[j][e];
                tote += c;
                if (j < w) woff += c;
            }
            if (pred[e])
                g_rows[k * N_ + base + run + woff + __popc(b[e] & lmask)]
                    = t0 + 4 * tid + e;
            run += tote;
        }
        base += run;
        __syncthreads();
    }
    if (tid == 0) g_cnt[k] = base;
}

// ---------------------------------------------------------------------------
// main_k helpers
// ---------------------------------------------------------------------------
__device__ __forceinline__ void process8(const float4* x, const int* srows, int i,
                                         float4 ck, float& ax, float& ay,
                                         float& az, float& aw,
                                         float invd, float* loss, int l) {
    float s[8];
#pragma unroll
    for (int j = 0; j < 8; j++) {
        float dx = x[j].x - ck.x, dy = x[j].y - ck.y;
        float dz = x[j].z - ck.z, dw = x[j].w - ck.w;
        s[j] = dx * dx + dy * dy + dz * dz + dw * dw;
        ax += x[j].x; ay += x[j].y; az += x[j].z; aw += x[j].w;
    }
    // multi-value reduce: 8 values across 32 lanes in 16 shuffles
    float cc[4];
#pragma unroll
    for (int p = 0; p < 4; p++) {
        float t0 = __shfl_xor_sync(0xFFFFFFFFu, s[2 * p], 16);
        float t1 = __shfl_xor_sync(0xFFFFFFFFu, s[2 * p + 1], 16);
        cc[p] = (l & 16) ? (s[2 * p + 1] + t1) : (s[2 * p] + t0);
    }
    float dd_[2];
#pragma unroll
    for (int p = 0; p < 2; p++) {
        float t0 = __shfl_xor_sync(0xFFFFFFFFu, cc[2 * p], 8);
        float t1 = __shfl_xor_sync(0xFFFFFFFFu, cc[2 * p + 1], 8);
        dd_[p] = (l & 8) ? (cc[2 * p + 1] + t1) : (cc[2 * p] + t0);
    }
    float t0 = __shfl_xor_sync(0xFFFFFFFFu, dd_[0], 4);
    float t1 = __shfl_xor_sync(0xFFFFFFFFu, dd_[1], 4);
    float e  = (l & 4) ? (dd_[1] + t1) : (dd_[0] + t0);
    e += __shfl_xor_sync(0xFFFFFFFFu, e, 2);
    e += __shfl_xor_sync(0xFFFFFFFFu, e, 1);
    // lane 4m holds total for row j = bit-reverse3(m)
    if ((l & 3) == 0) {
        int mm = l >> 2;
        int j = ((mm & 1) << 2) | (mm & 2) | (mm >> 2);
        atomicAdd(loss + srows[i + j], e * invd);
    }
}

// main fused pass: block (chunk c, cluster k, segment s).
// Software-pipelined 8-row batches: batch i+1's LDGs issue before batch i's
// reduce chain, hiding the ~130cyc shuffle dependency under memory latency.
__global__ void __launch_bounds__(TPB) main_k(const float* __restrict__ X,
                                              const float* __restrict__ C,
                                              float* __restrict__ out) {
    int c   = blockIdx.x;
    int k   = blockIdx.y;
    int seg = blockIdx.z;
    int tid = threadIdx.x;
    int l   = tid & 31;
    int col = c * CHUNK + 4 * tid;

    float4 ck = *reinterpret_cast<const float4*>(C + k * F_ + col);
    float ax = 0.f, ay = 0.f, az = 0.f, aw = 0.f;
    int   cnt  = g_cnt[k];
    float invd = g_invden[k];
    float* loss = out;                          // loss at out[0..N)

    int r0 = (cnt * seg) / S_;
    int r1 = (cnt * (seg + 1)) / S_;

    __shared__ int srows[TPB];
    const int* rl = g_rows + k * N_;

    for (int rb = r0; rb < r1; rb += TPB) {
        int m = min(TPB, r1 - rb);
        if (tid < m) srows[tid] = rl[rb + tid];
        __syncthreads();
        int i = 0;
        if (m >= 8) {
            float4 x[8];
#pragma unroll
            for (int j = 0; j < 8; j++)
                x[j] = *reinterpret_cast<const float4*>(
                    X + (size_t)srows[j] * F_ + col);
#pragma unroll 2
            for (i = 0; i + 16 <= m; i += 8) {
                float4 y[8];
#pragma unroll
                for (int j = 0; j < 8; j++)
                    y[j] = *reinterpret_cast<const float4*>(
                        X + (size_t)srows[i + 8 + j] * F_ + col);
                process8(x, srows, i, ck, ax, ay, az, aw, invd, loss, l);
#pragma unroll
                for (int j = 0; j < 8; j++) x[j] = y[j];
            }
            process8(x, srows, i, ck, ax, ay, az, aw, invd, loss, l);
            i += 8;
        }
        for (; i < m; i++) {                    // tail rows
            float4 x = *reinterpret_cast<const float4*>(
                X + (size_t)srows[i] * F_ + col);
            float dx = x.x - ck.x, dy = x.y - ck.y;
            float dz = x.z - ck.z, dw = x.w - ck.w;
            float s = dx * dx + dy * dy + dz * dz + dw * dw;
            ax += x.x; ay += x.y; az += x.z; aw += x.w;
#pragma unroll
            for (int o = 16; o; o >>= 1)
                s += __shfl_xor_sync(0xFFFFFFFFu, s, o);
            if (l == 0) atomicAdd(loss + srows[i], s * invd);
        }
        __syncthreads();
    }

    float4 p4 = make_float4(ax, ay, az, aw);
    *reinterpret_cast<float4*>(g_sx + ((size_t)seg * K_ + k) * F_ + col) = p4;
}

// fold segment partials + epilogue: new_cluster = ck - g*ak*(Sx - cnt*ck)
__global__ void reduce_k(const float* __restrict__ C, float* __restrict__ out) {
    int t  = blockIdx.x * TPB + threadIdx.x;    // over K_*F_/4
    int k  = t / (F_ / 4);
    int cv = t % (F_ / 4);
    float4 sum = make_float4(0.f, 0.f, 0.f, 0.f);
#pragma unroll
    for (int s = 0; s < S_; s++) {
        float4 v = *reinterpret_cast<const float4*>(
            g_sx + ((size_t)s * K_ + k) * F_ + 4 * cv);
        sum.x += v.x; sum.y += v.y; sum.z += v.z; sum.w += v.w;
    }
    float4 ck = reinterpret_cast<const float4*>(C + k * F_)[cv];
    float ga = GAMMA_F * g_ak[k];
    float fc = (float)g_cnt[k];
    float4 o;
    o.x = ck.x - ga * (sum.x - fc * ck.x);
    o.y = ck.y - ga * (sum.y - fc * ck.y);
    o.z = ck.z - ga * (sum.z - fc * ck.z);
    o.w = ck.w - ga * (sum.w - fc * ck.w);
    reinterpret_cast<float4*>(out + N_ + k * F_)[cv] = o;
}

extern "C" void kernel_launch(void* const* d_in, const int* in_sizes, int n_in,
                              void* d_out, int out_size) {
    const float* X  = (const float*)d_in[0];   // features [N,F]
    const float* L  = (const float*)d_in[1];   // labels   [N,K] one-hot
    const float* C  = (const float*)d_in[2];   // cluster  [K,F]
    const float* CW = (const float*)d_in[3];   // class_weight [K]
    float* out = (float*)d_out;                // [loss(N) | new_cluster(K*F)]

    prep_k   <<<K_, 256>>>(C, CW);
    idx_k    <<<(N_ * 4) / TPB, TPB>>>(L, out);
    bucket_k <<<K_, 256>>>();
    main_k   <<<dim3(NCHUNK, K_, S_), TPB>>>(X, C, out);
    reduce_k <<<(K_ * F_ / 4) / TPB, TPB>>>(C, out);
}

// round 8
// speedup vs baseline: 3.8891x; 1.0833x over previous
#include <cuda_runtime.h>

#define N_      16384
#define K_      64
#define F_      2048
#define NCHUNK  4
#define CHUNK   512          // floats per F-chunk (128 threads x float4)
#define TPB     128
#define S_      16           // row segments per cluster
#define ALPHA_F 1.0f
#define GAMMA_F 1.0f

// ---- scratch (static device globals: allocation-free) ----
__device__ int   g_rows[K_ * N_];        // per-cluster member row lists (stride N_)
__device__ int   g_cnt[K_];
__device__ float g_ak[K_];               // cw[k] / (row_sum[k]+alpha)
__device__ float g_invden[K_];           // 1 / (row_sum[k]+alpha)
__device__ float g_sx[K_ * F_];          // atomic column-sum accumulators (512 KB)
__device__ int   g_done[K_ * NCHUNK];    // per-(k,chunk) completion counters

// ---------------------------------------------------------------------------
// prep_k: block k computes rs_k = sum_j ||c_k - c_j||^2 directly (C stays in
// L2: 64 blocks x 512KB = 32MB L2 traffic), then ak/invden.
// Also zero-inits g_cnt and g_done for this call (idempotent on replay).
// ---------------------------------------------------------------------------
__global__ void __launch_bounds__(256) prep_k(const float* __restrict__ C,
                                              const float* __restrict__ cw) {
    int k = blockIdx.x, tid = threadIdx.x;
    if (tid == 0) g_cnt[k] = 0;
    if (tid < NCHUNK) g_done[k * NCHUNK + tid] = 0;
    // each thread owns 8 columns: [8*tid, 8*tid+8)
    float4 a0 = *reinterpret_cast<const float4*>(C + k * F_ + 8 * tid);
    float4 a1 = *reinterpret_cast<const float4*>(C + k * F_ + 8 * tid + 4);
    float acc = 0.f;
#pragma unroll 4
    for (int j = 0; j < K_; j++) {
        float4 b0 = *reinterpret_cast<const float4*>(C + j * F_ + 8 * tid);
        float4 b1 = *reinterpret_cast<const float4*>(C + j * F_ + 8 * tid + 4);
        float d0 = a0.x - b0.x, d1 = a0.y - b0.y, d2 = a0.z - b0.z, d3 = a0.w - b0.w;
        float d4 = a1.x - b1.x, d5 = a1.y - b1.y, d6 = a1.z - b1.z, d7 = a1.w - b1.w;
        acc += d0 * d0 + d1 * d1 + d2 * d2 + d3 * d3
             + d4 * d4 + d5 * d5 + d6 * d6 + d7 * d7;
    }
#pragma unroll
    for (int o = 16; o; o >>= 1) acc += __shfl_xor_sync(0xFFFFFFFFu, acc, o);
    __shared__ float sw_[8];
    int w = tid >> 5, l = tid & 31;
    if (l == 0) sw_[w] = acc;
    __syncthreads();
    if (tid == 0) {
        float rs = 0.f;
#pragma unroll
        for (int i = 0; i < 8; i++) rs += sw_[i];
        float inv = 1.f / (rs + ALPHA_F);
        g_invden[k] = inv;
        g_ak[k]     = cw[k] * inv;
    }
}

// ---------------------------------------------------------------------------
// assign_k: fused idx + bucketing. 4 threads per row; labels exact one-hot
// => idx = sum_i v[i]*i (exact fp32). Slot via atomicAdd on g_cnt (arrival
// order; only permutes float-summation order downstream).
// Also zero-inits loss region of d_out and the g_sx accumulators.
// ---------------------------------------------------------------------------
__global__ void __launch_bounds__(256) assign_k(const float* __restrict__ labels,
                                                float* __restrict__ loss) {
    int t = blockIdx.x * 256 + threadIdx.x;          // 65536 threads
    // zero g_sx: 131072 floats = 65536 float2
    reinterpret_cast<float2*>(g_sx)[t] = make_float2(0.f, 0.f);

    int row = t >> 2, part = t & 3;
    const float4* p = reinterpret_cast<const float4*>(labels + row * K_) + part * 4;
    float acc = 0.f;
#pragma unroll
    for (int j = 0; j < 4; j++) {
        float4 v = p[j];
        float base = (float)(part * 16 + j * 4);
        acc += v.x * base + v.y * (base + 1.f) + v.z * (base + 2.f) + v.w * (base + 3.f);
    }
    acc += __shfl_xor_sync(0xFFFFFFFFu, acc, 1);
    acc += __shfl_xor_sync(0xFFFFFFFFu, acc, 2);
    if (part == 0) {
        int k = (int)(acc + 0.5f);
        int slot = atomicAdd(&g_cnt[k], 1);
        g_rows[k * N_ + slot] = row;
        loss[row] = 0.f;
    }
}

// ---------------------------------------------------------------------------
// process4: distances + accumulate + 9-shuffle multi-value loss reduce.
// ---------------------------------------------------------------------------
__device__ __forceinline__ void process4(const float4* x, const int* srows, int i,
                                         float4 ck, float& ax, float& ay,
                                         float& az, float& aw,
                                         float invd, float* loss, int l) {
    float s[4];
#pragma unroll
    for (int j = 0; j < 4; j++) {
        float dx = x[j].x - ck.x, dy = x[j].y - ck.y;
        float dz = x[j].z - ck.z, dw = x[j].w - ck.w;
        s[j] = dx * dx + dy * dy + dz * dz + dw * dw;
        ax += x[j].x; ay += x[j].y; az += x[j].z; aw += x[j].w;
    }
    float cc[2];
#pragma unroll
    for (int p = 0; p < 2; p++) {
        float t0 = __shfl_xor_sync(0xFFFFFFFFu, s[2 * p], 16);
        float t1 = __shfl_xor_sync(0xFFFFFFFFu, s[2 * p + 1], 16);
        cc[p] = (l & 16) ? (s[2 * p + 1] + t1) : (s[2 * p] + t0);
    }
    float t0 = __shfl_xor_sync(0xFFFFFFFFu, cc[0], 8);
    float t1 = __shfl_xor_sync(0xFFFFFFFFu, cc[1], 8);
    float e  = (l & 8) ? (cc[1] + t1) : (cc[0] + t0);
    e += __shfl_xor_sync(0xFFFFFFFFu, e, 4);
    e += __shfl_xor_sync(0xFFFFFFFFu, e, 2);
    e += __shfl_xor_sync(0xFFFFFFFFu, e, 1);
    // lane 8m holds total for row j = ((m&... ) mapping below
    if ((l & 7) == 0) {
        int j = ((l >> 4) & 1) | (((l >> 3) & 1) << 1);  // l=0,8,16,24 -> 0,2,1,3
        atomicAdd(loss + srows[i + j], e * invd);
    }
}

// ---------------------------------------------------------------------------
// main_k: block (chunk c, cluster k, segment s). Depth-4 double-buffered
// pipeline (fits ~64-72 regs -> ~7 blocks/SM). Column-sum partials are
// atomically accumulated into g_sx; the LAST finishing block per (k,c)
// performs the new_cluster epilogue (fused reduce).
// ---------------------------------------------------------------------------
__global__ void __launch_bounds__(TPB, 7) main_k(const float* __restrict__ X,
                                                 const float* __restrict__ C,
                                                 float* __restrict__ out) {
    int c   = blockIdx.x;
    int k   = blockIdx.y;
    int seg = blockIdx.z;
    int tid = threadIdx.x;
    int l   = tid & 31;
    int col = c * CHUNK + 4 * tid;

    float4 ck = *reinterpret_cast<const float4*>(C + k * F_ + col);
    float ax = 0.f, ay = 0.f, az = 0.f, aw = 0.f;
    int   cnt  = g_cnt[k];
    float invd = g_invden[k];
    float* loss = out;                          // loss at out[0..N)

    int r0 = (cnt * seg) / S_;
    int r1 = (cnt * (seg + 1)) / S_;

    __shared__ int srows[TPB];
    const int* rl = g_rows + k * N_;

    for (int rb = r0; rb < r1; rb += TPB) {
        int m = min(TPB, r1 - rb);
        if (tid < m) srows[tid] = rl[rb + tid];
        __syncthreads();
        int i = 0;
        if (m >= 4) {
            float4 x[4];
#pragma unroll
            for (int j = 0; j < 4; j++)
                x[j] = *reinterpret_cast<const float4*>(
                    X + (size_t)srows[j] * F_ + col);
            for (i = 0; i + 8 <= m; i += 4) {
                float4 y[4];
#pragma unroll
                for (int j = 0; j < 4; j++)
                    y[j] = *reinterpret_cast<const float4*>(
                        X + (size_t)srows[i + 4 + j] * F_ + col);
                process4(x, srows, i, ck, ax, ay, az, aw, invd, loss, l);
#pragma unroll
                for (int j = 0; j < 4; j++) x[j] = y[j];
            }
            process4(x, srows, i, ck, ax, ay, az, aw, invd, loss, l);
            i += 4;
        }
        for (; i < m; i++) {                    // tail rows
            float4 x = *reinterpret_cast<const float4*>(
                X + (size_t)srows[i] * F_ + col);
            float dx = x.x - ck.x, dy = x.y - ck.y;
            float dz = x.z - ck.z, dw = x.w - ck.w;
            float s = dx * dx + dy * dy + dz * dz + dw * dw;
            ax += x.x; ay += x.y; az += x.z; aw += x.w;
#pragma unroll
            for (int o = 16; o; o >>= 1)
                s += __shfl_xor_sync(0xFFFFFFFFu, s, o);
            if (l == 0) atomicAdd(loss + srows[i], s * invd);
        }
        __syncthreads();
    }

    // accumulate segment partials into g_sx
    float* sx = g_sx + k * F_ + col;
    atomicAdd(sx + 0, ax);
    atomicAdd(sx + 1, ay);
    atomicAdd(sx + 2, az);
    atomicAdd(sx + 3, aw);

    // last block per (k, chunk) does the new_cluster epilogue
    __threadfence();
    __shared__ int amLast;
    if (tid == 0)
        amLast = (atomicAdd(&g_done[k * NCHUNK + c], 1) == S_ - 1);
    __syncthreads();
    if (amLast) {
        float sx0 = __ldcg(sx + 0), sx1 = __ldcg(sx + 1);
        float sx2 = __ldcg(sx + 2), sx3 = __ldcg(sx + 3);
        float ga = GAMMA_F * g_ak[k];
        float fc = (float)cnt;
        float4 o;
        o.x = ck.x - ga * (sx0 - fc * ck.x);
        o.y = ck.y - ga * (sx1 - fc * ck.y);
        o.z = ck.z - ga * (sx2 - fc * ck.z);
        o.w = ck.w - ga * (sx3 - fc * ck.w);
        *reinterpret_cast<float4*>(out + N_ + k * F_ + col) = o;
        if (tid == 0) g_done[k * NCHUNK + c] = 0;   // reset for graph replay
    }
}

extern "C" void kernel_launch(void* const* d_in, const int* in_sizes, int n_in,
                              void* d_out, int out_size) {
    const float* X  = (const float*)d_in[0];   // features [N,F]
    const float* L  = (const float*)d_in[1];   // labels   [N,K] one-hot
    const float* C  = (const float*)d_in[2];   // cluster  [K,F]
    const float* CW = (const float*)d_in[3];   // class_weight [K]
    float* out = (float*)d_out;                // [loss(N) | new_cluster(K*F)]

    prep_k   <<<K_, 256>>>(C, CW);
    assign_k <<<(N_ * 4) / 256, 256>>>(L, out);
    main_k   <<<dim3(NCHUNK, K_, S_), TPB>>>(X, C, out);
}

// round 9
// speedup vs baseline: 4.3625x; 1.1217x over previous
#include <cuda_runtime.h>

#define N_      16384
#define K_      64
#define F_      2048
#define NCHUNK  4
#define CHUNK   512          // floats per F-chunk (128 threads x float4)
#define TPB     128
#define S_      16           // row segments per cluster
#define AB_     256          // assign blocks in setup_k
#define PB_     256          // prep blocks in setup_k (64 k x 4 col-chunks)
#define ALPHA_F 1.0f
#define GAMMA_F 1.0f

// ---- scratch (static device globals: allocation-free, zero-initialized) ----
__device__ int   g_rows[K_ * N_];        // per-cluster member row lists (stride N_)
__device__ int   g_cnt[K_];              // member counts (reset by main_k)
__device__ float g_rs[K_];               // pairwise dist row-sums (reset by main_k)
__device__ int   g_pdone[K_];            // prep col-chunk arrival (self-reset)
__device__ float g_ak[K_];               // cw[k] / (rs[k]+alpha)
__device__ float g_invden[K_];           // 1 / (rs[k]+alpha)
__device__ float g_sx[K_ * F_];          // atomic column-sum accumulators
__device__ int   g_done[K_ * NCHUNK];    // per-(k,chunk) epilogue arrival (self-reset)
__device__ int   g_kdone[K_];            // per-k global arrival (self-reset)

// ---------------------------------------------------------------------------
// setup_k: ONE kernel, two independent block families.
//  blocks [0,AB_):    assign — idx from exact one-hot (sum v[i]*i), slot via
//                     atomicAdd(g_cnt), zero g_sx and the loss region.
//  blocks [AB_,512):  prep — (k, col-chunk c) computes partial
//                     sum_j ||c_k - c_j||^2 over 512 cols; atomicAdd into
//                     g_rs[k]; last-of-4 computes invden/ak.
// ---------------------------------------------------------------------------
__global__ void __launch_bounds__(256) setup_k(const float* __restrict__ C,
                                               const float* __restrict__ cw,
                                               const float* __restrict__ labels,
                                               float* __restrict__ loss) {
    int b = blockIdx.x, tid = threadIdx.x;
    if (b < AB_) {
        int t = b * 256 + tid;                       // 65536 threads
        // zero g_sx: 131072 floats = 65536 float2
        reinterpret_cast<float2*>(g_sx)[t] = make_float2(0.f, 0.f);

        int row = t >> 2, part = t & 3;
        const float4* p =
            reinterpret_cast<const float4*>(labels + row * K_) + part * 4;
        float acc = 0.f;
#pragma unroll
        for (int j = 0; j < 4; j++) {
            float4 v = p[j];
            float base = (float)(part * 16 + j * 4);
            acc += v.x * base + v.y * (base + 1.f)
                 + v.z * (base + 2.f) + v.w * (base + 3.f);
        }
        acc += __shfl_xor_sync(0xFFFFFFFFu, acc, 1);
        acc += __shfl_xor_sync(0xFFFFFFFFu, acc, 2);
        if (part == 0) {
            int k = (int)(acc + 0.5f);
            int slot = atomicAdd(&g_cnt[k], 1);
            g_rows[k * N_ + slot] = row;
            loss[row] = 0.f;
        }
    } else {
        int pb = b - AB_;
        int k = pb >> 2, c = pb & 3;
        int col = c * 512 + 2 * tid;                 // 256 threads x 2 cols
        float2 a = *reinterpret_cast<const float2*>(C + k * F_ + col);
        float acc = 0.f;
#pragma unroll 8
        for (int j = 0; j < K_; j++) {
            float2 bv = *reinterpret_cast<const float2*>(C + j * F_ + col);
            float d0 = a.x - bv.x, d1 = a.y - bv.y;
            acc += d0 * d0 + d1 * d1;
        }
#pragma unroll
        for (int o = 16; o; o >>= 1)
            acc += __shfl_xor_sync(0xFFFFFFFFu, acc, o);
        __shared__ float sw_[8];
        int w = tid >> 5, l = tid & 31;
        if (l == 0) sw_[w] = acc;
        __syncthreads();
        if (tid == 0) {
            float bs = 0.f;
#pragma unroll
            for (int i = 0; i < 8; i++) bs += sw_[i];
            atomicAdd(&g_rs[k], bs);
            __threadfence();
            if (atomicAdd(&g_pdone[k], 1) == 3) {    // last col-chunk for k
                float rs = *(volatile float*)&g_rs[k];
                float inv = 1.f / (rs + ALPHA_F);
                g_invden[k] = inv;
                g_ak[k]     = cw[k] * inv;
                g_pdone[k]  = 0;                     // self-reset for replay
            }
        }
    }
}

// ---------------------------------------------------------------------------
// process4: distances + accumulate + 9-shuffle multi-value loss reduce.
// ---------------------------------------------------------------------------
__device__ __forceinline__ void process4(const float4* x, const int* srows, int i,
                                         float4 ck, float& ax, float& ay,
                                         float& az, float& aw,
                                         float invd, float* loss, int l) {
    float s[4];
#pragma unroll
    for (int j = 0; j < 4; j++) {
        float dx = x[j].x - ck.x, dy = x[j].y - ck.y;
        float dz = x[j].z - ck.z, dw = x[j].w - ck.w;
        s[j] = dx * dx + dy * dy + dz * dz + dw * dw;
        ax += x[j].x; ay += x[j].y; az += x[j].z; aw += x[j].w;
    }
    float cc[2];
#pragma unroll
    for (int p = 0; p < 2; p++) {
        float t0 = __shfl_xor_sync(0xFFFFFFFFu, s[2 * p], 16);
        float t1 = __shfl_xor_sync(0xFFFFFFFFu, s[2 * p + 1], 16);
        cc[p] = (l & 16) ? (s[2 * p + 1] + t1) : (s[2 * p] + t0);
    }
    float t0 = __shfl_xor_sync(0xFFFFFFFFu, cc[0], 8);
    float t1 = __shfl_xor_sync(0xFFFFFFFFu, cc[1], 8);
    float e  = (l & 8) ? (cc[1] + t1) : (cc[0] + t0);
    e += __shfl_xor_sync(0xFFFFFFFFu, e, 4);
    e += __shfl_xor_sync(0xFFFFFFFFu, e, 2);
    e += __shfl_xor_sync(0xFFFFFFFFu, e, 1);
    if ((l & 7) == 0) {
        int j = ((l >> 4) & 1) | (((l >> 3) & 1) << 1);  // l=0,8,16,24 -> 0,2,1,3
        atomicAdd(loss + srows[i + j], e * invd);
    }
}

// ---------------------------------------------------------------------------
// main_k: block (chunk c, cluster k, segment s). Depth-4 double-buffered
// pipeline. Column partials -> atomic g_sx; last block per (k,c) writes
// new_cluster; globally-last block per k resets g_cnt/g_rs/g_kdone for the
// next graph replay.
// ---------------------------------------------------------------------------
__global__ void __launch_bounds__(TPB, 7) main_k(const float* __restrict__ X,
                                                 const float* __restrict__ C,
                                                 float* __restrict__ out) {
    int c   = blockIdx.x;
    int k   = blockIdx.y;
    int seg = blockIdx.z;
    int tid = threadIdx.x;
    int l   = tid & 31;
    int col = c * CHUNK + 4 * tid;

    float4 ck = *reinterpret_cast<const float4*>(C + k * F_ + col);
    float ax = 0.f, ay = 0.f, az = 0.f, aw = 0.f;
    int   cnt  = g_cnt[k];
    float invd = g_invden[k];
    float* loss = out;                          // loss at out[0..N)

    int r0 = (cnt * seg) / S_;
    int r1 = (cnt * (seg + 1)) / S_;

    __shared__ int srows[TPB];
    const int* rl = g_rows + k * N_;

    for (int rb = r0; rb < r1; rb += TPB) {
        int m = min(TPB, r1 - rb);
        if (tid < m) srows[tid] = rl[rb + tid];
        __syncthreads();
        int i = 0;
        if (m >= 4) {
            float4 x[4];
#pragma unroll
            for (int j = 0; j < 4; j++)
                x[j] = *reinterpret_cast<const float4*>(
                    X + (size_t)srows[j] * F_ + col);
            for (i = 0; i + 8 <= m; i += 4) {
                float4 y[4];
#pragma unroll
                for (int j = 0; j < 4; j++)
                    y[j] = *reinterpret_cast<const float4*>(
                        X + (size_t)srows[i + 4 + j] * F_ + col);
                process4(x, srows, i, ck, ax, ay, az, aw, invd, loss, l);
#pragma unroll
                for (int j = 0; j < 4; j++) x[j] = y[j];
            }
            process4(x, srows, i, ck, ax, ay, az, aw, invd, loss, l);
            i += 4;
        }
        for (; i < m; i++) {                    // tail rows
            float4 x = *reinterpret_cast<const float4*>(
                X + (size_t)srows[i] * F_ + col);
            float dx = x.x - ck.x, dy = x.y - ck.y;
            float dz = x.z - ck.z, dw = x.w - ck.w;
            float s = dx * dx + dy * dy + dz * dz + dw * dw;
            ax += x.x; ay += x.y; az += x.z; aw += x.w;
#pragma unroll
            for (int o = 16; o; o >>= 1)
                s += __shfl_xor_sync(0xFFFFFFFFu, s, o);
            if (l == 0) atomicAdd(loss + srows[i], s * invd);
        }
        __syncthreads();
    }

    // accumulate segment partials into g_sx
    float* sx = g_sx + k * F_ + col;
    atomicAdd(sx + 0, ax);
    atomicAdd(sx + 1, ay);
    atomicAdd(sx + 2, az);
    atomicAdd(sx + 3, aw);

    // last block per (k, chunk) does the new_cluster epilogue
    __threadfence();
    __shared__ int amLast;
    if (tid == 0)
        amLast = (atomicAdd(&g_done[k * NCHUNK + c], 1) == S_ - 1);
    __syncthreads();
    if (amLast) {
        float sx0 = __ldcg(sx + 0), sx1 = __ldcg(sx + 1);
        float sx2 = __ldcg(sx + 2), sx3 = __ldcg(sx + 3);
        float ga = GAMMA_F * g_ak[k];
        float fc = (float)cnt;
        float4 o;
        o.x = ck.x - ga * (sx0 - fc * ck.x);
        o.y = ck.y - ga * (sx1 - fc * ck.y);
        o.z = ck.z - ga * (sx2 - fc * ck.z);
        o.w = ck.w - ga * (sx3 - fc * ck.w);
        *reinterpret_cast<float4*>(out + N_ + k * F_ + col) = o;
        if (tid == 0) g_done[k * NCHUNK + c] = 0;   // reset for graph replay
    }

    // globally-last block of cluster k resets per-k state for next replay.
    // Safe: counter full => every block of k has already read g_cnt/g_invden.
    if (tid == 0) {
        if (atomicAdd(&g_kdone[k], 1) == S_ * NCHUNK - 1) {
            g_kdone[k] = 0;
            g_cnt[k]   = 0;
            g_rs[k]    = 0.f;
        }
    }
}

extern "C" void kernel_launch(void* const* d_in, const int* in_sizes, int n_in,
                              void* d_out, int out_size) {
    const float* X  = (const float*)d_in[0];   // features [N,F]
    const float* L  = (const float*)d_in[1];   // labels   [N,K] one-hot
    const float* C  = (const float*)d_in[2];   // cluster  [K,F]
    const float* CW = (const float*)d_in[3];   // class_weight [K]
    float* out = (float*)d_out;                // [loss(N) | new_cluster(K*F)]

    setup_k <<<AB_ + PB_, 256>>>(C, CW, L, out);
    main_k  <<<dim3(NCHUNK, K_, S_), TPB>>>(X, C, out);
}

// round 12
// speedup vs baseline: 4.7699x; 1.0934x over previous
#include <cuda_runtime.h>
#include <cstdint>

#define N_      16384
#define K_      64
#define F_      2048
#define NCHUNK  2            // column chunks of 1024 floats
#define CHUNK   1024
#define TPB     128          // each thread owns 8 floats (32B) of the chunk
#define S_      8            // row segments per cluster
#define D_      7            // cp.async pipeline stages
#define TILE_R  256          // row-id staging tile
#define AB_     256          // assign blocks in setup_k
#define PB_     256          // prep blocks in setup_k
#define ALPHA_F 1.0f
#define GAMMA_F 1.0f

// ---- scratch (static device globals: allocation-free, zero-initialized) ----
__device__ int   g_rows[K_ * N_];        // per-cluster member row lists
__device__ int   g_cnt[K_];              // member counts (reset by main_k)
__device__ float g_rs[K_];               // pairwise dist row-sums (reset by main_k)
__device__ int   g_pdone[K_];            // prep arrival (self-reset)
__device__ float g_ak[K_];               // cw[k] / (rs[k]+alpha)
__device__ float g_invden[K_];           // 1 / (rs[k]+alpha)
__device__ float g_sx[K_ * F_];          // atomic column-sum accumulators
__device__ int   g_done[K_ * NCHUNK];    // per-(k,chunk) epilogue arrival (self-reset)
__device__ int   g_kdone[K_];            // per-k global arrival (self-reset)

__device__ __forceinline__ void cp16(unsigned s, const float* g) {
    asm volatile("cp.async.cg.shared.global [%0], [%1], 16;"
                 :: "r"(s), "l"(g) : "memory");
}

// ---------------------------------------------------------------------------
// setup_k: ONE kernel, two independent block families.
//  blocks [0,AB_):    assign — idx from exact one-hot (sum v[i]*i), slot via
//                     atomicAdd(g_cnt), zero g_sx and the loss region.
//  blocks [AB_,512):  prep — (k, col-chunk) partial sum_j ||c_k - c_j||^2;
//                     atomicAdd into g_rs[k]; last-of-4 computes invden/ak.
// ---------------------------------------------------------------------------
__global__ void __launch_bounds__(256) setup_k(const float* __restrict__ C,
                                               const float* __restrict__ cw,
                                               const float* __restrict__ labels,
                                               float* __restrict__ loss) {
    int b = blockIdx.x, tid = threadIdx.x;
    if (b < AB_) {
        int t = b * 256 + tid;                       // 65536 threads
        reinterpret_cast<float2*>(g_sx)[t] = make_float2(0.f, 0.f);

        int row = t >> 2, part = t & 3;
        const float4* p =
            reinterpret_cast<const float4*>(labels + row * K_) + part * 4;
        float acc = 0.f;
#pragma unroll
        for (int j = 0; j < 4; j++) {
            float4 v = p[j];
            float base = (float)(part * 16 + j * 4);
            acc += v.x * base + v.y * (base + 1.f)
                 + v.z * (base + 2.f) + v.w * (base + 3.f);
        }
        acc += __shfl_xor_sync(0xFFFFFFFFu, acc, 1);
        acc += __shfl_xor_sync(0xFFFFFFFFu, acc, 2);
        if (part == 0) {
            int k = (int)(acc + 0.5f);
            int slot = atomicAdd(&g_cnt[k], 1);
            g_rows[k * N_ + slot] = row;
            loss[row] = 0.f;
        }
    } else {
        int pb = b - AB_;
        int k = pb >> 2, c = pb & 3;
        int col = c * 512 + 2 * tid;
        float2 a = *reinterpret_cast<const float2*>(C + k * F_ + col);
        float acc = 0.f;
#pragma unroll 8
        for (int j = 0; j < K_; j++) {
            float2 bv = *reinterpret_cast<const float2*>(C + j * F_ + col);
            float d0 = a.x - bv.x, d1 = a.y - bv.y;
            acc += d0 * d0 + d1 * d1;
        }
#pragma unroll
        for (int o = 16; o; o >>= 1)
            acc += __shfl_xor_sync(0xFFFFFFFFu, acc, o);
        __shared__ float sw_[8];
        int w = tid >> 5, l = tid & 31;
        if (l == 0) sw_[w] = acc;
        __syncthreads();
        if (tid == 0) {
            float bs = 0.f;
#pragma unroll
            for (int i = 0; i < 8; i++) bs += sw_[i];
            atomicAdd(&g_rs[k], bs);
            __threadfence();
            if (atomicAdd(&g_pdone[k], 1) == 3) {
                float rs = *(volatile float*)&g_rs[k];
                float inv = 1.f / (rs + ALPHA_F);
                g_invden[k] = inv;
                g_ak[k]     = cw[k] * inv;
                g_pdone[k]  = 0;
            }
        }
    }
}

// ---------------------------------------------------------------------------
// main_k: block (chunk c, cluster k, segment s). Rows staged through smem by
// a barrier-free cp.async pipeline (each thread copies and reads ONLY its own
// 32B per stage -> no cross-thread smem hazards). D_=7 stages x 4KB.
// Column partials -> atomic g_sx; last block per (k,c) writes new_cluster.
// RACE FIX vs R11: __threadfence + __syncthreads BEFORE the g_done arrival,
// so ALL warps' sx atomics are ordered before this block's arrival is visible.
// ---------------------------------------------------------------------------
__global__ void __launch_bounds__(TPB) main_k(const float* __restrict__ X,
                                              const float* __restrict__ C,
                                              float* __restrict__ out) {
    __shared__ float buf[D_ * CHUNK];
    __shared__ int   srows[TILE_R];
    __shared__ int   amLast;

    int c   = blockIdx.x;
    int k   = blockIdx.y;
    int seg = blockIdx.z;
    int tid = threadIdx.x;
    int l   = tid & 31;
    int colt = c * CHUNK + tid * 8;

    float4 ck0 = *reinterpret_cast<const float4*>(C + k * F_ + colt);
    float4 ck1 = *reinterpret_cast<const float4*>(C + k * F_ + colt + 4);
    float4 ac0 = make_float4(0.f, 0.f, 0.f, 0.f);
    float4 ac1 = make_float4(0.f, 0.f, 0.f, 0.f);

    int   cnt  = g_cnt[k];
    float invd = g_invden[k];
    float* loss = out;                          // loss at out[0..N)

    int r0 = (cnt * seg) / S_;
    int r1 = (cnt * (seg + 1)) / S_;
    const int* rl = g_rows + k * N_;

    unsigned sb = (unsigned)__cvta_generic_to_shared(buf) + tid * 32u;

    for (int t0 = r0; t0 < r1; t0 += TILE_R) {
        int tl = min(TILE_R, r1 - t0);
        __syncthreads();                        // protect srows reuse
        for (int t = tid; t < tl; t += TPB) srows[t] = rl[t0 + t];
        __syncthreads();

        // pipeline prologue: fill up to D_ stages
#pragma unroll
        for (int s = 0; s < D_; s++) {
            if (s < tl) {
                const float* g = X + (size_t)srows[s] * F_ + colt;
                unsigned a = sb + (unsigned)s * (CHUNK * 4u);
                cp16(a, g); cp16(a + 16u, g + 4);
            }
            asm volatile("cp.async.commit_group;" ::: "memory");
        }

        int st = 0;
        for (int r = 0; r < tl; r++) {
            asm volatile("cp.async.wait_group %0;" :: "n"(D_ - 1) : "memory");
            const float4* bp =
                reinterpret_cast<const float4*>(buf + st * CHUNK + tid * 8);
            float4 x0 = bp[0], x1 = bp[1];

            float d0 = x0.x - ck0.x, d1 = x0.y - ck0.y;
            float d2 = x0.z - ck0.z, d3 = x0.w - ck0.w;
            float d4 = x1.x - ck1.x, d5 = x1.y - ck1.y;
            float d6 = x1.z - ck1.z, d7 = x1.w - ck1.w;
            float s = d0 * d0 + d1 * d1 + d2 * d2 + d3 * d3
                    + d4 * d4 + d5 * d5 + d6 * d6 + d7 * d7;
            ac0.x += x0.x; ac0.y += x0.y; ac0.z += x0.z; ac0.w += x0.w;
            ac1.x += x1.x; ac1.y += x1.y; ac1.z += x1.z; ac1.w += x1.w;
#pragma unroll
            for (int o = 16; o; o >>= 1)
                s += __shfl_xor_sync(0xFFFFFFFFu, s, o);
            if (l == 0) atomicAdd(loss + srows[r], s * invd);

            int nr = r + D_;
            if (nr < tl) {
                const float* g = X + (size_t)srows[nr] * F_ + colt;
                unsigned a = sb + (unsigned)st * (CHUNK * 4u);
                cp16(a, g); cp16(a + 16u, g + 4);
            }
            asm volatile("cp.async.commit_group;" ::: "memory");
            if (++st == D_) st = 0;
        }
        asm volatile("cp.async.wait_group 0;" ::: "memory");
    }

    // accumulate segment partials into g_sx
    float* sx = g_sx + k * F_ + colt;
    atomicAdd(sx + 0, ac0.x); atomicAdd(sx + 1, ac0.y);
    atomicAdd(sx + 2, ac0.z); atomicAdd(sx + 3, ac0.w);
    atomicAdd(sx + 4, ac1.x); atomicAdd(sx + 5, ac1.y);
    atomicAdd(sx + 6, ac1.z); atomicAdd(sx + 7, ac1.w);

    // ---- RACE FIX: every thread fences its partials, then the BLOCK
    // barrier guarantees all warps' atomics are ordered before tid0's
    // arrival increment is observable by the amLast reader. ----
    __threadfence();
    __syncthreads();
    if (tid == 0)
        amLast = (atomicAdd(&g_done[k * NCHUNK + c], 1) == S_ - 1);
    __syncthreads();
    if (amLast) {
        float4 s0 = __ldcg(reinterpret_cast<const float4*>(sx));
        float4 s1 = __ldcg(reinterpret_cast<const float4*>(sx) + 1);
        float ga = GAMMA_F * g_ak[k];
        float fc = (float)cnt;
        float4 o0, o1;
        o0.x = ck0.x - ga * (s0.x - fc * ck0.x);
        o0.y = ck0.y - ga * (s0.y - fc * ck0.y);
        o0.z = ck0.z - ga * (s0.z - fc * ck0.z);
        o0.w = ck0.w - ga * (s0.w - fc * ck0.w);
        o1.x = ck1.x - ga * (s1.x - fc * ck1.x);
        o1.y = ck1.y - ga * (s1.y - fc * ck1.y);
        o1.z = ck1.z - ga * (s1.z - fc * ck1.z);
        o1.w = ck1.w - ga * (s1.w - fc * ck1.w);
        *reinterpret_cast<float4*>(out + N_ + k * F_ + colt)     = o0;
        *reinterpret_cast<float4*>(out + N_ + k * F_ + colt + 4) = o1;
        if (tid == 0) g_done[k * NCHUNK + c] = 0;   // reset for graph replay
    }

    // globally-last block of cluster k resets per-k state for next replay.
    // Safe: all warps passed the barriers above, so every block of k has
    // already read g_cnt/g_invden before its arrival here.
    if (tid == 0) {
        if (atomicAdd(&g_kdone[k], 1) == S_ * NCHUNK - 1) {
            g_kdone[k] = 0;
            g_cnt[k]   = 0;
            g_rs[k]    = 0.f;
        }
    }
}

extern "C" void kernel_launch(void* const* d_in, const int* in_sizes, int n_in,
                              void* d_out, int out_size) {
    const float* X  = (const float*)d_in[0];   // features [N,F]
    const float* L  = (const float*)d_in[1];   // labels   [N,K] one-hot
    const float* C  = (const float*)d_in[2];   // cluster  [K,F]
    const float* CW = (const float*)d_in[3];   // class_weight [K]
    float* out = (float*)d_out;                // [loss(N) | new_cluster(K*F)]

    setup_k <<<AB_ + PB_, 256>>>(C, CW, L, out);
    main_k  <<<dim3(NCHUNK, K_, S_), TPB>>>(X, C, out);
}